// round 14
// baseline (speedup 1.0000x reference)
#include <cuda_runtime.h>
#include <math.h>

// B=2, N=9216, C=512, HEAD=8, d=64, SR=4, H=W=96 -> Nkv=576, R=32
#define SCALING 0.125f

// ---------------------------------------------------------------------------
// Scratch
// ---------------------------------------------------------------------------
__device__ float g_q    [9437184];  // (B,N,C) prescaled*0.125, tf32
__device__ float g_xs   [589824];   // (B*576,512) post-LN, tf32
__device__ float g_lv   [589824];
__device__ float g_k    [589824];   // (B*H,576,64) tf32
__device__ float g_v    [589824];   // (B*H,64,576) TRANSPOSED, tf32
__device__ float g_ctx  [9437184];  // tf32
__device__ float g_w2   [4194304];  // 512x8192 reordered conv weight
__device__ float g_part [4718592];  // split-K partials
__device__ float g_bq8  [512];      // b_q * 0.125
__device__ float g_weffq[262144];   // w_q + 0.125*lBq@lAq, tf32
__device__ float g_weffv[262144];   // 0.125*lBv@lAv, tf32

// ---------------------------------------------------------------------------
// helpers
// ---------------------------------------------------------------------------
__device__ __forceinline__ unsigned f2tf(float x) {
    unsigned u;
    asm("cvt.rna.tf32.f32 %0, %1;" : "=r"(u) : "f"(x));
    return u;
}
__device__ __forceinline__ unsigned f2tf_u(unsigned x) {
    unsigned u;
    asm("cvt.rna.tf32.f32 %0, %1;" : "=r"(u) : "f"(__uint_as_float(x)));
    return u;
}
__device__ __forceinline__ void mma8(float* c, const unsigned* a, const unsigned* b) {
    asm volatile(
        "mma.sync.aligned.m16n8k8.row.col.f32.tf32.tf32.f32 "
        "{%0,%1,%2,%3}, {%4,%5,%6,%7}, {%8,%9}, {%0,%1,%2,%3};"
        : "+f"(c[0]), "+f"(c[1]), "+f"(c[2]), "+f"(c[3])
        : "r"(a[0]), "r"(a[1]), "r"(a[2]), "r"(a[3]),
          "r"(b[0]), "r"(b[1]));
}
__device__ __forceinline__ void ldsm4(unsigned* r, unsigned addr) {
    asm volatile(
        "ldmatrix.sync.aligned.m8n8.x4.shared.b16 {%0,%1,%2,%3}, [%4];"
        : "=r"(r[0]), "=r"(r[1]), "=r"(r[2]), "=r"(r[3]) : "r"(addr));
}
__device__ __forceinline__ void cpa16(unsigned dst, const void* src) {
    asm volatile("cp.async.cg.shared.global [%0], [%1], 16;" :: "r"(dst), "l"(src));
}
__device__ __forceinline__ void cpa_commit() {
    asm volatile("cp.async.commit_group;" ::: "memory");
}
__device__ __forceinline__ void cpa_wait0() {
    asm volatile("cp.async.wait_group 0;" ::: "memory");
}

// Weff[o][i] = tf32( (base? base[o][i]:0) + SCALING * sum_r lB[o][r]*lA[r][i] )
__global__ void make_weff(const float* __restrict__ wbase,
                          const float* __restrict__ lB,   // 512x32
                          const float* __restrict__ lA,   // 32x512
                          float* __restrict__ out)        // 512x512
{
    const int i = blockIdx.x * 256 + threadIdx.x;
    const int col = i & 511, row = i >> 9;
    float s = 0.f;
#pragma unroll 8
    for (int r = 0; r < 32; r++)
        s += lB[row * 32 + r] * lA[r * 512 + col];
    s *= SCALING;
    if (wbase) s += wbase[i];
    out[i] = __uint_as_float(f2tf(s));
}

__global__ void prep_bq(const float* __restrict__ bq, float* __restrict__ bq8)
{
    const int i = blockIdx.x * 256 + threadIdx.x;
    if (i < 512) bq8[i] = bq[i] * 0.125f;
}

// ---------------------------------------------------------------------------
// tf32 GEMM, BK=32, 2-stage cp.async pipeline, ldmatrix frags.
// Operands may be raw fp32: fragments are tf32-rounded in registers
// post-ldmatrix (idempotent for pre-rounded data -> bit-identical numerics).
//   C = scale*(A@B^T) (+bias)  [round_out]
// BM=128, BN in {64,128}; 256 threads; warps 4(M)x2(N).
// REQUIRES kchunk%32==0.  CONV=1: A gathered with SR-conv im2col mapping.
// dyn smem: 2*(128+BN)*36*4 bytes.
// ---------------------------------------------------------------------------
template <int BN, int CONV>
__global__ void __launch_bounds__(256, 2)
gemm_tf32(int M, int N, int K,
          const float* __restrict__ A, int lda,
          const float* __restrict__ B, int ldb,
          const float* __restrict__ bias,
          float scale,
          float* __restrict__ C, int ldc,
          int kchunk, float* __restrict__ part,
          int round_out)
{
    constexpr int NI = BN / 16;
    constexpr int P  = 36;
    extern __shared__ unsigned gsm[];
    unsigned* AsU = gsm;                   // 2 x 128 x P
    unsigned* BsU = gsm + 2 * 128 * P;     // 2 x BN x P

    const int t    = threadIdx.x;
    const int lane = t & 31, w = t >> 5;
    const int g  = lane >> 2, tg = lane & 3;
    const int wm = w >> 1,  wn = w & 1;
    const long m0 = (long)blockIdx.y * 128;
    const int  n0 = blockIdx.x * BN;
    const int  kb = blockIdx.z * kchunk;

    const int lrow = t >> 3;
    const int lko  = (t & 7) * 4;

    const int tS = lane >> 3;
    const unsigned asB = (unsigned)__cvta_generic_to_shared(AsU);
    const unsigned bsB = (unsigned)__cvta_generic_to_shared(BsU);
    const unsigned aOff = ((wm * 32 + (tS & 1) * 8 + (lane & 7)) * P
                           + (tS >> 1) * 4) * 4;
    const unsigned bOff = ((wn * (BN / 2) + (tS >> 1) * 8 + (lane & 7)) * P
                           + (tS & 1) * 4) * 4;

    float acc[2][NI][4];
#pragma unroll
    for (int mi = 0; mi < 2; mi++)
#pragma unroll
        for (int ni = 0; ni < NI; ni++)
#pragma unroll
            for (int c = 0; c < 4; c++) acc[mi][ni][c] = 0.f;

    long cr[4];
    if (CONV) {
#pragma unroll
        for (int i = 0; i < 4; i++) {
            int m = (int)m0 + i * 32 + lrow;
            int b = m / 576, p = m % 576, py = p / 24, px = p % 24;
            cr[i] = (long)b * 9216 + (py * 4) * 96 + px * 4;
        }
    }

    const int nIter = kchunk >> 5;

    auto issueTile = [&](int idx, int s) {
        const unsigned aS = asB + s * (128 * P * 4);
        const unsigned bS = bsB + s * (BN * P * 4);
        const int k0 = kb + (idx << 5);
        if (CONV) {
            const int tap = k0 >> 9;
            const int ci  = (k0 & 511) + lko;
            const long toff = (long)((tap >> 2) * 96 + (tap & 3)) * 512 + ci;
#pragma unroll
            for (int i = 0; i < 4; i++)
                cpa16(aS + ((i * 32 + lrow) * P + lko) * 4,
                      A + cr[i] * 512 + toff);
        } else {
#pragma unroll
            for (int i = 0; i < 4; i++)
                cpa16(aS + ((i * 32 + lrow) * P + lko) * 4,
                      A + (m0 + i * 32 + lrow) * lda + k0 + lko);
        }
#pragma unroll
        for (int i = 0; i < BN / 32; i++)
            cpa16(bS + ((i * 32 + lrow) * P + lko) * 4,
                  B + (long)(n0 + i * 32 + lrow) * ldb + k0 + lko);
        cpa_commit();
    };

    issueTile(0, 0);

    for (int it = 0; it < nIter; it++) {
        cpa_wait0();
        __syncthreads();
        if (it + 1 < nIter) issueTile(it + 1, (it + 1) & 1);

        const int s = it & 1;
        const unsigned aB = asB + s * (128 * P * 4) + aOff;
        const unsigned bB = bsB + s * (BN * P * 4) + bOff;
#pragma unroll
        for (int kk = 0; kk < 32; kk += 8) {
            unsigned af[2][4], bf[NI][2];
#pragma unroll
            for (int mi = 0; mi < 2; mi++) {
                ldsm4(af[mi], aB + mi * (16 * P * 4) + kk * 4);
#pragma unroll
                for (int j = 0; j < 4; j++) af[mi][j] = f2tf_u(af[mi][j]);
            }
#pragma unroll
            for (int p = 0; p < NI / 2; p++) {
                unsigned q4[4];
                ldsm4(q4, bB + p * (16 * P * 4) + kk * 4);
#pragma unroll
                for (int j = 0; j < 4; j++) q4[j] = f2tf_u(q4[j]);
                bf[2 * p][0] = q4[0]; bf[2 * p][1] = q4[1];
                bf[2 * p + 1][0] = q4[2]; bf[2 * p + 1][1] = q4[3];
            }
#pragma unroll
            for (int mi = 0; mi < 2; mi++)
#pragma unroll
                for (int ni = 0; ni < NI; ni++)
                    mma8(acc[mi][ni], af[mi], bf[ni]);
        }
    }

    if (gridDim.z == 1) {
#pragma unroll
        for (int mi = 0; mi < 2; mi++) {
            const long r0 = m0 + wm * 32 + mi * 16 + g;
            const long r1 = r0 + 8;
#pragma unroll
            for (int ni = 0; ni < NI; ni++) {
                const int c = n0 + wn * (BN / 2) + ni * 8 + 2 * tg;
                float v00 = scale * acc[mi][ni][0];
                float v01 = scale * acc[mi][ni][1];
                float v10 = scale * acc[mi][ni][2];
                float v11 = scale * acc[mi][ni][3];
                if (bias) {
                    float b0 = bias[c], b1 = bias[c + 1];
                    v00 += b0; v01 += b1; v10 += b0; v11 += b1;
                }
                if (round_out) {
                    v00 = __uint_as_float(f2tf(v00));
                    v01 = __uint_as_float(f2tf(v01));
                    v10 = __uint_as_float(f2tf(v10));
                    v11 = __uint_as_float(f2tf(v11));
                }
                *(float2*)(C + r0 * ldc + c) = make_float2(v00, v01);
                *(float2*)(C + r1 * ldc + c) = make_float2(v10, v11);
            }
        }
    } else {
        float* Pp = part + (long)blockIdx.z * M * ldc;
#pragma unroll
        for (int mi = 0; mi < 2; mi++) {
            const long r0 = m0 + wm * 32 + mi * 16 + g;
            const long r1 = r0 + 8;
#pragma unroll
            for (int ni = 0; ni < NI; ni++) {
                const int c = n0 + wn * (BN / 2) + ni * 8 + 2 * tg;
                *(float2*)(Pp + r0 * ldc + c) =
                    make_float2(acc[mi][ni][0], acc[mi][ni][1]);
                *(float2*)(Pp + r1 * ldc + c) =
                    make_float2(acc[mi][ni][2], acc[mi][ni][3]);
            }
        }
    }
}

// ---------------------------------------------------------------------------
// Fused conv split-K reduce + bias + LayerNorm -> xs (tf32-rounded).
// ---------------------------------------------------------------------------
__global__ void reduce_ln(const float* __restrict__ part,
                          const float* __restrict__ bias,
                          const float* __restrict__ gam,
                          const float* __restrict__ bet,
                          float* __restrict__ out)
{
    const int row = blockIdx.x;
    const int t   = threadIdx.x;
    float v[4];
#pragma unroll
    for (int j = 0; j < 4; j++) {
        const int col = t + j * 128;
        float s = bias[col];
        const long off = (long)row * 512 + col;
#pragma unroll
        for (int z = 0; z < 8; z++) s += part[z * 589824 + off];
        v[j] = s;
    }
    float s  = v[0] + v[1] + v[2] + v[3];
    float s2 = v[0]*v[0] + v[1]*v[1] + v[2]*v[2] + v[3]*v[3];
#pragma unroll
    for (int o = 16; o > 0; o >>= 1) {
        s  += __shfl_xor_sync(0xffffffffu, s,  o);
        s2 += __shfl_xor_sync(0xffffffffu, s2, o);
    }
    __shared__ float ss[4], ss2[4];
    if ((t & 31) == 0) { ss[t >> 5] = s; ss2[t >> 5] = s2; }
    __syncthreads();
    s  = ss[0]  + ss[1]  + ss[2]  + ss[3];
    s2 = ss2[0] + ss2[1] + ss2[2] + ss2[3];
    const float mean = s * (1.f / 512.f);
    const float var  = s2 * (1.f / 512.f) - mean * mean;
    const float inv  = rsqrtf(var + 1e-5f);
    float* o = out + (long)row * 512;
#pragma unroll
    for (int j = 0; j < 4; j++) {
        const int col = t + j * 128;
        o[col] = __uint_as_float(f2tf((v[j] - mean) * inv * gam[col] + bet[col]));
    }
}

// ---------------------------------------------------------------------------
// Fused kv split-K reduce + bias + head split + LoRA-v fixup.
// k: [bh][m][dd] tf32.  v: [bh][dd][m] TRANSPOSED, tf32.
// ---------------------------------------------------------------------------
__global__ void reduce_build_kv(const float* __restrict__ part,
                                const float* __restrict__ bias,
                                const float* __restrict__ lv,
                                float* __restrict__ k, float* __restrict__ vt)
{
    const int idx = blockIdx.x * 256 + threadIdx.x;
    const int dd = idx & 63;
    const int m  = (idx >> 6) % 576;
    const int bh = idx / 36864;
    const int h  = bh & 7, b = bh >> 3;
    const int ck = h * 64 + dd;
    const long mrow = (long)(b * 576 + m) * 1024;
    float sk = bias[ck], sv = bias[512 + ck];
#pragma unroll
    for (int z = 0; z < 4; z++) {
        sk += part[z * 1179648 + mrow + ck];
        sv += part[z * 1179648 + mrow + 512 + ck];
    }
    k[idx] = __uint_as_float(f2tf(sk));
    float vv = sv + lv[(long)b * 294912 + h * 36864 + m * 64 + dd];
    vt[(long)bh * 36864 + dd * 576 + m] = __uint_as_float(f2tf(vv));
}

// w2[co][(i*4+j)*512 + ci] = tf32(w_sr[co][ci][i][j])
__global__ void reorder_w_kernel(const float* __restrict__ w,
                                 float* __restrict__ w2)
{
    const int tid = blockIdx.x * 256 + threadIdx.x;
    const int ci = tid & 511;
    const int s  = (tid >> 9) & 15;
    const int co = tid >> 13;
    w2[tid] = __uint_as_float(f2tf(w[(long)co * 8192 + ci * 16 + s]));
}

// ---------------------------------------------------------------------------
// FA2-style tf32 attention, cp.async + double-buffered K/V.
// q/k/v arrive pre-tf32 from producers (NOT re-rounded here).
// ---------------------------------------------------------------------------
#define TPw 68
#define ATTN_SMEM (TPw * 384 * 4)

__global__ void __launch_bounds__(256, 2)
attn_flash(const float* __restrict__ qb,
           const float* __restrict__ kb,
           const float* __restrict__ vtb,
           float* __restrict__ ctx)
{
    extern __shared__ float sm[];
    float*    Sw = sm;
    unsigned* KV = (unsigned*)(sm + 128 * TPw);

    const int t    = threadIdx.x;
    const int lane = t & 31, w = t >> 5;
    const int g  = lane >> 2, tg = lane & 3;
    const int bh = blockIdx.y, b = bh >> 3, h = bh & 7;
    const int n0 = blockIdx.x * 128;

    const int tS = lane >> 3;
    const unsigned swB = (unsigned)__cvta_generic_to_shared(Sw);
    const unsigned kvB = (unsigned)__cvta_generic_to_shared(KV);
    const unsigned aOff = ((w * 16 + (tS & 1) * 8 + (lane & 7)) * TPw
                           + (tS >> 1) * 4) * 4;
    const unsigned bOff = (((tS >> 1) * 8 + (lane & 7)) * TPw
                           + (tS & 1) * 4) * 4;
    constexpr unsigned BUFB = 128 * TPw * 4;
    constexpr unsigned VOFF = 64 * TPw * 4;

    auto loadQ = [&]() {
#pragma unroll
        for (int i = 0; i < 8; i++) {
            int c = i * 256 + t;
            int row = c >> 4, off = (c & 15) * 4;
            cpa16(swB + (row * TPw + off) * 4,
                  qb + (long)(b * 9216 + n0 + row) * 512 + h * 64 + off);
        }
    };
    auto loadKV = [&](int ch, int buf) {
#pragma unroll
        for (int i = 0; i < 4; i++) {
            int c = i * 256 + t;
            int row = c >> 4, off = (c & 15) * 4;
            cpa16(kvB + buf * BUFB + (row * TPw + off) * 4,
                  kb + (long)(bh * 576 + ch * 64 + row) * 64 + off);
            cpa16(kvB + buf * BUFB + VOFF + (row * TPw + off) * 4,
                  vtb + (long)bh * 36864 + row * 576 + ch * 64 + off);
        }
    };

    loadQ();
    loadKV(0, 0);
    cpa_commit();
    cpa_wait0();
    __syncthreads();

    unsigned Qf[8][4];
#pragma unroll
    for (int kk = 0; kk < 8; kk++)
        ldsm4(Qf[kk], swB + aOff + kk * 32);

    float O[8][4];
#pragma unroll
    for (int nd = 0; nd < 8; nd++)
#pragma unroll
        for (int c = 0; c < 4; c++) O[nd][c] = 0.f;
    float m0 = -1e30f, l0 = 0.f, m1 = -1e30f, l1 = 0.f;

    int buf = 0;
    for (int ch = 0; ch < 9; ch++) {
        const bool more = (ch + 1 < 9);
        if (more) { loadKV(ch + 1, buf ^ 1); cpa_commit(); }

        const unsigned ksB = kvB + buf * BUFB + bOff;
        const unsigned vsB = kvB + buf * BUFB + VOFF + bOff;

        float acc[8][4];
#pragma unroll
        for (int ni = 0; ni < 8; ni++)
#pragma unroll
            for (int c = 0; c < 4; c++) acc[ni][c] = 0.f;
#pragma unroll
        for (int kk = 0; kk < 8; kk++) {
            unsigned bf[8][2];
#pragma unroll
            for (int p = 0; p < 4; p++) {
                unsigned q4[4];
                ldsm4(q4, ksB + p * (16 * TPw * 4) + kk * 32);
                bf[2 * p][0] = q4[0]; bf[2 * p][1] = q4[1];
                bf[2 * p + 1][0] = q4[2]; bf[2 * p + 1][1] = q4[3];
            }
#pragma unroll
            for (int ni = 0; ni < 8; ni++)
                mma8(acc[ni], Qf[kk], bf[ni]);
        }

        float cm0 = -1e30f, cm1 = -1e30f;
#pragma unroll
        for (int ni = 0; ni < 8; ni++) {
            cm0 = fmaxf(cm0, fmaxf(acc[ni][0], acc[ni][1]));
            cm1 = fmaxf(cm1, fmaxf(acc[ni][2], acc[ni][3]));
        }
        cm0 = fmaxf(cm0, __shfl_xor_sync(0xffffffffu, cm0, 1));
        cm0 = fmaxf(cm0, __shfl_xor_sync(0xffffffffu, cm0, 2));
        cm1 = fmaxf(cm1, __shfl_xor_sync(0xffffffffu, cm1, 1));
        cm1 = fmaxf(cm1, __shfl_xor_sync(0xffffffffu, cm1, 2));
        const float nm0 = fmaxf(m0, cm0), nm1 = fmaxf(m1, cm1);
        const float al0 = __expf(m0 - nm0), al1 = __expf(m1 - nm1);
        float sum0 = 0.f, sum1 = 0.f;
#pragma unroll
        for (int ni = 0; ni < 8; ni++) {
            float e0 = __expf(acc[ni][0] - nm0);
            float e1 = __expf(acc[ni][1] - nm0);
            float e2 = __expf(acc[ni][2] - nm1);
            float e3 = __expf(acc[ni][3] - nm1);
            acc[ni][0] = e0; acc[ni][1] = e1; acc[ni][2] = e2; acc[ni][3] = e3;
            sum0 += e0 + e1; sum1 += e2 + e3;
        }
        sum0 += __shfl_xor_sync(0xffffffffu, sum0, 1);
        sum0 += __shfl_xor_sync(0xffffffffu, sum0, 2);
        sum1 += __shfl_xor_sync(0xffffffffu, sum1, 1);
        sum1 += __shfl_xor_sync(0xffffffffu, sum1, 2);
        l0 = l0 * al0 + sum0; l1 = l1 * al1 + sum1;
        m0 = nm0; m1 = nm1;
#pragma unroll
        for (int nd = 0; nd < 8; nd++) {
            O[nd][0] *= al0; O[nd][1] *= al0;
            O[nd][2] *= al1; O[nd][3] *= al1;
        }

        float* SwW = Sw + w * 16 * TPw;
#pragma unroll
        for (int ni = 0; ni < 8; ni++) {
            *(float2*)&SwW[g * TPw + ni * 8 + 2 * tg] =
                make_float2(acc[ni][0], acc[ni][1]);
            *(float2*)&SwW[(g + 8) * TPw + ni * 8 + 2 * tg] =
                make_float2(acc[ni][2], acc[ni][3]);
        }
        __syncwarp();

#pragma unroll
        for (int kk = 0; kk < 8; kk++) {
            unsigned pa[4];
            ldsm4(pa, swB + aOff + kk * 32);
            unsigned bf[8][2];
#pragma unroll
            for (int p = 0; p < 4; p++) {
                unsigned q4[4];
                ldsm4(q4, vsB + p * (16 * TPw * 4) + kk * 32);
                bf[2 * p][0] = q4[0]; bf[2 * p][1] = q4[1];
                bf[2 * p + 1][0] = q4[2]; bf[2 * p + 1][1] = q4[3];
            }
#pragma unroll
            for (int nd = 0; nd < 8; nd++)
                mma8(O[nd], pa, bf[nd]);
        }

        if (more) {
            cpa_wait0();
            __syncthreads();
            buf ^= 1;
        }
    }

    const float inv0 = 1.f / l0, inv1 = 1.f / l1;
    const long row0 = (long)(b * 9216 + n0 + w * 16 + g) * 512 + h * 64;
    const long row1 = row0 + 8 * 512;
#pragma unroll
    for (int nd = 0; nd < 8; nd++) {
        const int c = nd * 8 + 2 * tg;
        *(float2*)(ctx + row0 + c) =
            make_float2(__uint_as_float(f2tf(O[nd][0] * inv0)),
                        __uint_as_float(f2tf(O[nd][1] * inv0)));
        *(float2*)(ctx + row1 + c) =
            make_float2(__uint_as_float(f2tf(O[nd][2] * inv1)),
                        __uint_as_float(f2tf(O[nd][3] * inv1)));
    }
}

// ---------------------------------------------------------------------------
// Launch pipeline (no cross-stream evX dependency anymore)
// ---------------------------------------------------------------------------
extern "C" void kernel_launch(void* const* d_in, const int* in_sizes, int n_in,
                              void* d_out, int out_size)
{
    (void)in_sizes; (void)n_in; (void)out_size;
    const float* x      = (const float*)d_in[0];
    const float* w_q    = (const float*)d_in[1];
    const float* b_q    = (const float*)d_in[2];
    const float* w_kv   = (const float*)d_in[3];
    const float* b_kv   = (const float*)d_in[4];
    const float* w_proj = (const float*)d_in[5];
    const float* b_proj = (const float*)d_in[6];
    const float* w_sr   = (const float*)d_in[7];
    const float* b_sr   = (const float*)d_in[8];
    const float* ln_g   = (const float*)d_in[9];
    const float* ln_b   = (const float*)d_in[10];
    const float* lAq    = (const float*)d_in[11];
    const float* lBq    = (const float*)d_in[12];
    const float* lAv    = (const float*)d_in[13];
    const float* lBv    = (const float*)d_in[14];

    float *q, *xs, *lv, *k, *v, *ctx, *w2, *part;
    float *bq8, *weffq, *weffv;
    cudaGetSymbolAddress((void**)&q,     g_q);
    cudaGetSymbolAddress((void**)&xs,    g_xs);
    cudaGetSymbolAddress((void**)&lv,    g_lv);
    cudaGetSymbolAddress((void**)&k,     g_k);
    cudaGetSymbolAddress((void**)&v,     g_v);
    cudaGetSymbolAddress((void**)&ctx,   g_ctx);
    cudaGetSymbolAddress((void**)&w2,    g_w2);
    cudaGetSymbolAddress((void**)&part,  g_part);
    cudaGetSymbolAddress((void**)&bq8,   g_bq8);
    cudaGetSymbolAddress((void**)&weffq, g_weffq);
    cudaGetSymbolAddress((void**)&weffv, g_weffv);

    static cudaStream_t s2 = nullptr;
    static cudaEvent_t evF = nullptr, evJ = nullptr;
    if (!s2) {
        cudaStreamCreateWithFlags(&s2, cudaStreamNonBlocking);
        cudaEventCreateWithFlags(&evF, cudaEventDisableTiming);
        cudaEventCreateWithFlags(&evJ, cudaEventDisableTiming);
    }

    dim3 blk(256);
    const int smem128 = 2 * 256 * 36 * 4;   // 73728
    cudaFuncSetAttribute(gemm_tf32<128, 0>,
                         cudaFuncAttributeMaxDynamicSharedMemorySize, smem128);
    cudaFuncSetAttribute(gemm_tf32<128, 1>,
                         cudaFuncAttributeMaxDynamicSharedMemorySize, smem128);
    cudaFuncSetAttribute(attn_flash,
                         cudaFuncAttributeMaxDynamicSharedMemorySize, ATTN_SMEM);

    // ---- fork ----
    cudaEventRecord(evF, 0);
    cudaStreamWaitEvent(s2, evF, 0);

    // ---- side chain (stream s2): xs / k / v ----
    reorder_w_kernel<<<16384, blk, 0, s2>>>(w_sr, w2);
    make_weff<<<1024, blk, 0, s2>>>(nullptr, lBv, lAv, weffv);
    gemm_tf32<128, 1><<<dim3(4, 9, 8), blk, smem128, s2>>>(
        1152, 512, 8192, x, 512, w2, 8192, nullptr, 1.f, nullptr, 512,
        1024, part, 0);
    reduce_ln<<<1152, 128, 0, s2>>>(part, b_sr, ln_g, ln_b, xs);
    gemm_tf32<128, 0><<<dim3(8, 9, 4), blk, smem128, s2>>>(
        1152, 1024, 512, xs, 512, w_kv, 512, nullptr, 1.f, nullptr, 1024,
        128, part, 0);
    gemm_tf32<128, 0><<<dim3(4, 9, 1), blk, smem128, s2>>>(
        1152, 512, 512, xs, 512, weffv, 512, nullptr, 1.f, lv, 512,
        512, nullptr, 0);
    reduce_build_kv<<<2304, blk, 0, s2>>>(part, b_kv, lv, k, v);
    cudaEventRecord(evJ, s2);

    // ---- main chain: q = (X @ Weff_q^T) * 0.125 + bq8, tf32-rounded ----
    prep_bq<<<2, blk>>>(b_q, bq8);
    make_weff<<<1024, blk>>>(w_q, lBq, lAq, weffq);
    gemm_tf32<128, 0><<<dim3(4, 144, 1), blk, smem128>>>(
        18432, 512, 512, x, 512, weffq, 512, bq8, 0.125f, q, 512,
        512, nullptr, 1);

    // ---- join ----
    cudaStreamWaitEvent(0, evJ, 0);

    attn_flash<<<dim3(72, 16), blk, ATTN_SMEM>>>(q, k, v, ctx);

    gemm_tf32<128, 0><<<dim3(4, 144, 1), blk, smem128>>>(
        18432, 512, 512, ctx, 512, w_proj, 512, b_proj, 1.f, (float*)d_out,
        512, 512, nullptr, 0);
}

// round 15
// speedup vs baseline: 1.0505x; 1.0505x over previous
#include <cuda_runtime.h>
#include <math.h>

// B=2, N=9216, C=512, HEAD=8, d=64, SR=4, H=W=96 -> Nkv=576, R=32
#define SCALING 0.125f

// ---------------------------------------------------------------------------
// Scratch
// ---------------------------------------------------------------------------
__device__ float g_q    [9437184];  // (B,N,C) prescaled*0.125, tf32
__device__ float g_xs   [589824];   // (B*576,512) post-LN, tf32
__device__ float g_lv   [589824];
__device__ float g_k    [589824];   // (B*H,576,64) tf32
__device__ float g_v    [589824];   // (B*H,64,576) TRANSPOSED, tf32
__device__ float g_ctx  [9437184];  // tf32
__device__ float g_w2   [4194304];  // 512x8192 reordered conv weight, tf32
__device__ float g_part [4718592];  // split-K partials
__device__ float g_bq8  [512];      // b_q * 0.125
__device__ float g_weffq[262144];   // w_q + 0.125*lBq@lAq, tf32
__device__ float g_weffv[262144];   // 0.125*lBv@lAv, tf32
__device__ float g_wkv2 [524288];   // w_kv tf32
__device__ float g_wp2  [262144];   // w_proj tf32

// ---------------------------------------------------------------------------
// helpers
// ---------------------------------------------------------------------------
__device__ __forceinline__ unsigned f2tf(float x) {
    unsigned u;
    asm("cvt.rna.tf32.f32 %0, %1;" : "=r"(u) : "f"(x));
    return u;
}
__device__ __forceinline__ unsigned f2tf_u(unsigned x) {
    unsigned u;
    asm("cvt.rna.tf32.f32 %0, %1;" : "=r"(u) : "f"(__uint_as_float(x)));
    return u;
}
__device__ __forceinline__ void mma8(float* c, const unsigned* a, const unsigned* b) {
    asm volatile(
        "mma.sync.aligned.m16n8k8.row.col.f32.tf32.tf32.f32 "
        "{%0,%1,%2,%3}, {%4,%5,%6,%7}, {%8,%9}, {%0,%1,%2,%3};"
        : "+f"(c[0]), "+f"(c[1]), "+f"(c[2]), "+f"(c[3])
        : "r"(a[0]), "r"(a[1]), "r"(a[2]), "r"(a[3]),
          "r"(b[0]), "r"(b[1]));
}
__device__ __forceinline__ void ldsm4(unsigned* r, unsigned addr) {
    asm volatile(
        "ldmatrix.sync.aligned.m8n8.x4.shared.b16 {%0,%1,%2,%3}, [%4];"
        : "=r"(r[0]), "=r"(r[1]), "=r"(r[2]), "=r"(r[3]) : "r"(addr));
}
__device__ __forceinline__ void cpa16(unsigned dst, const void* src) {
    asm volatile("cp.async.cg.shared.global [%0], [%1], 16;" :: "r"(dst), "l"(src));
}
__device__ __forceinline__ void cpa_commit() {
    asm volatile("cp.async.commit_group;" ::: "memory");
}
__device__ __forceinline__ void cpa_wait0() {
    asm volatile("cp.async.wait_group 0;" ::: "memory");
}

// elementwise tf32 round
__global__ void cvt_tf32(const float* __restrict__ in, float* __restrict__ out)
{
    const int i = (blockIdx.x * 256 + threadIdx.x) * 4;
    float4 v = *(const float4*)(in + i);
    uint4 u;
    u.x = f2tf(v.x); u.y = f2tf(v.y); u.z = f2tf(v.z); u.w = f2tf(v.w);
    *(uint4*)(out + i) = u;
}

// Weff[o][i] = tf32( (base? base[o][i]:0) + SCALING * sum_r lB[o][r]*lA[r][i] )
__global__ void make_weff(const float* __restrict__ wbase,
                          const float* __restrict__ lB,   // 512x32
                          const float* __restrict__ lA,   // 32x512
                          float* __restrict__ out)        // 512x512
{
    const int i = blockIdx.x * 256 + threadIdx.x;
    const int col = i & 511, row = i >> 9;
    float s = 0.f;
#pragma unroll 8
    for (int r = 0; r < 32; r++)
        s += lB[row * 32 + r] * lA[r * 512 + col];
    s *= SCALING;
    if (wbase) s += wbase[i];
    out[i] = __uint_as_float(f2tf(s));
}

__global__ void prep_bq(const float* __restrict__ bq, float* __restrict__ bq8)
{
    const int i = blockIdx.x * 256 + threadIdx.x;
    if (i < 512) bq8[i] = bq[i] * 0.125f;
}

// ---------------------------------------------------------------------------
// tf32 GEMM, BK=32, 2-stage cp.async pipeline, ldmatrix frags.
// A may be raw fp32 (A-fragments tf32-rounded in registers, idempotent for
// pre-rounded data). B MUST be pre-rounded tf32 in gmem.
//   C = scale*(A@B^T) (+bias)  [round_out]
// BM=128, BN=128; 256 threads; warps 4(M)x2(N).  kchunk%32==0.
// CONV=1: A gathered with SR-conv im2col mapping.
// dyn smem: 2*256*36*4 bytes.
// ---------------------------------------------------------------------------
template <int BN, int CONV>
__global__ void __launch_bounds__(256, 2)
gemm_tf32(int M, int N, int K,
          const float* __restrict__ A, int lda,
          const float* __restrict__ B, int ldb,
          const float* __restrict__ bias,
          float scale,
          float* __restrict__ C, int ldc,
          int kchunk, float* __restrict__ part,
          int round_out)
{
    constexpr int NI = BN / 16;
    constexpr int P  = 36;
    extern __shared__ unsigned gsm[];
    unsigned* AsU = gsm;                   // 2 x 128 x P
    unsigned* BsU = gsm + 2 * 128 * P;     // 2 x BN x P

    const int t    = threadIdx.x;
    const int lane = t & 31, w = t >> 5;
    const int g  = lane >> 2, tg = lane & 3;
    const int wm = w >> 1,  wn = w & 1;
    const long m0 = (long)blockIdx.y * 128;
    const int  n0 = blockIdx.x * BN;
    const int  kb = blockIdx.z * kchunk;

    const int lrow = t >> 3;
    const int lko  = (t & 7) * 4;

    const int tS = lane >> 3;
    const unsigned asB = (unsigned)__cvta_generic_to_shared(AsU);
    const unsigned bsB = (unsigned)__cvta_generic_to_shared(BsU);
    const unsigned aOff = ((wm * 32 + (tS & 1) * 8 + (lane & 7)) * P
                           + (tS >> 1) * 4) * 4;
    const unsigned bOff = ((wn * (BN / 2) + (tS >> 1) * 8 + (lane & 7)) * P
                           + (tS & 1) * 4) * 4;

    float acc[2][NI][4];
#pragma unroll
    for (int mi = 0; mi < 2; mi++)
#pragma unroll
        for (int ni = 0; ni < NI; ni++)
#pragma unroll
            for (int c = 0; c < 4; c++) acc[mi][ni][c] = 0.f;

    long cr[4];
    if (CONV) {
#pragma unroll
        for (int i = 0; i < 4; i++) {
            int m = (int)m0 + i * 32 + lrow;
            int b = m / 576, p = m % 576, py = p / 24, px = p % 24;
            cr[i] = (long)b * 9216 + (py * 4) * 96 + px * 4;
        }
    }

    const int nIter = kchunk >> 5;

    auto issueTile = [&](int idx, int s) {
        const unsigned aS = asB + s * (128 * P * 4);
        const unsigned bS = bsB + s * (BN * P * 4);
        const int k0 = kb + (idx << 5);
        if (CONV) {
            const int tap = k0 >> 9;
            const int ci  = (k0 & 511) + lko;
            const long toff = (long)((tap >> 2) * 96 + (tap & 3)) * 512 + ci;
#pragma unroll
            for (int i = 0; i < 4; i++)
                cpa16(aS + ((i * 32 + lrow) * P + lko) * 4,
                      A + cr[i] * 512 + toff);
        } else {
#pragma unroll
            for (int i = 0; i < 4; i++)
                cpa16(aS + ((i * 32 + lrow) * P + lko) * 4,
                      A + (m0 + i * 32 + lrow) * lda + k0 + lko);
        }
#pragma unroll
        for (int i = 0; i < BN / 32; i++)
            cpa16(bS + ((i * 32 + lrow) * P + lko) * 4,
                  B + (long)(n0 + i * 32 + lrow) * ldb + k0 + lko);
        cpa_commit();
    };

    issueTile(0, 0);

    for (int it = 0; it < nIter; it++) {
        cpa_wait0();
        __syncthreads();
        if (it + 1 < nIter) issueTile(it + 1, (it + 1) & 1);

        const int s = it & 1;
        const unsigned aB = asB + s * (128 * P * 4) + aOff;
        const unsigned bB = bsB + s * (BN * P * 4) + bOff;
#pragma unroll
        for (int kk = 0; kk < 32; kk += 8) {
            unsigned af[2][4], bf[NI][2];
#pragma unroll
            for (int mi = 0; mi < 2; mi++) {
                ldsm4(af[mi], aB + mi * (16 * P * 4) + kk * 4);
#pragma unroll
                for (int j = 0; j < 4; j++) af[mi][j] = f2tf_u(af[mi][j]);
            }
#pragma unroll
            for (int p = 0; p < NI / 2; p++) {
                unsigned q4[4];
                ldsm4(q4, bB + p * (16 * P * 4) + kk * 4);
                bf[2 * p][0] = q4[0]; bf[2 * p][1] = q4[1];
                bf[2 * p + 1][0] = q4[2]; bf[2 * p + 1][1] = q4[3];
            }
#pragma unroll
            for (int mi = 0; mi < 2; mi++)
#pragma unroll
                for (int ni = 0; ni < NI; ni++)
                    mma8(acc[mi][ni], af[mi], bf[ni]);
        }
    }

    if (gridDim.z == 1) {
#pragma unroll
        for (int mi = 0; mi < 2; mi++) {
            const long r0 = m0 + wm * 32 + mi * 16 + g;
            const long r1 = r0 + 8;
#pragma unroll
            for (int ni = 0; ni < NI; ni++) {
                const int c = n0 + wn * (BN / 2) + ni * 8 + 2 * tg;
                float v00 = scale * acc[mi][ni][0];
                float v01 = scale * acc[mi][ni][1];
                float v10 = scale * acc[mi][ni][2];
                float v11 = scale * acc[mi][ni][3];
                if (bias) {
                    float b0 = bias[c], b1 = bias[c + 1];
                    v00 += b0; v01 += b1; v10 += b0; v11 += b1;
                }
                if (round_out) {
                    v00 = __uint_as_float(f2tf(v00));
                    v01 = __uint_as_float(f2tf(v01));
                    v10 = __uint_as_float(f2tf(v10));
                    v11 = __uint_as_float(f2tf(v11));
                }
                *(float2*)(C + r0 * ldc + c) = make_float2(v00, v01);
                *(float2*)(C + r1 * ldc + c) = make_float2(v10, v11);
            }
        }
    } else {
        float* Pp = part + (long)blockIdx.z * M * ldc;
#pragma unroll
        for (int mi = 0; mi < 2; mi++) {
            const long r0 = m0 + wm * 32 + mi * 16 + g;
            const long r1 = r0 + 8;
#pragma unroll
            for (int ni = 0; ni < NI; ni++) {
                const int c = n0 + wn * (BN / 2) + ni * 8 + 2 * tg;
                *(float2*)(Pp + r0 * ldc + c) =
                    make_float2(acc[mi][ni][0], acc[mi][ni][1]);
                *(float2*)(Pp + r1 * ldc + c) =
                    make_float2(acc[mi][ni][2], acc[mi][ni][3]);
            }
        }
    }
}

// ---------------------------------------------------------------------------
// Fused conv split-K reduce + bias + LayerNorm -> xs (tf32-rounded).
// ---------------------------------------------------------------------------
__global__ void reduce_ln(const float* __restrict__ part,
                          const float* __restrict__ bias,
                          const float* __restrict__ gam,
                          const float* __restrict__ bet,
                          float* __restrict__ out)
{
    const int row = blockIdx.x;
    const int t   = threadIdx.x;
    float v[4];
#pragma unroll
    for (int j = 0; j < 4; j++) {
        const int col = t + j * 128;
        float s = bias[col];
        const long off = (long)row * 512 + col;
#pragma unroll
        for (int z = 0; z < 8; z++) s += part[z * 589824 + off];
        v[j] = s;
    }
    float s  = v[0] + v[1] + v[2] + v[3];
    float s2 = v[0]*v[0] + v[1]*v[1] + v[2]*v[2] + v[3]*v[3];
#pragma unroll
    for (int o = 16; o > 0; o >>= 1) {
        s  += __shfl_xor_sync(0xffffffffu, s,  o);
        s2 += __shfl_xor_sync(0xffffffffu, s2, o);
    }
    __shared__ float ss[4], ss2[4];
    if ((t & 31) == 0) { ss[t >> 5] = s; ss2[t >> 5] = s2; }
    __syncthreads();
    s  = ss[0]  + ss[1]  + ss[2]  + ss[3];
    s2 = ss2[0] + ss2[1] + ss2[2] + ss2[3];
    const float mean = s * (1.f / 512.f);
    const float var  = s2 * (1.f / 512.f) - mean * mean;
    const float inv  = rsqrtf(var + 1e-5f);
    float* o = out + (long)row * 512;
#pragma unroll
    for (int j = 0; j < 4; j++) {
        const int col = t + j * 128;
        o[col] = __uint_as_float(f2tf((v[j] - mean) * inv * gam[col] + bet[col]));
    }
}

// ---------------------------------------------------------------------------
// Fused kv split-K reduce + bias + head split + LoRA-v fixup.
// k: [bh][m][dd] tf32.  v: [bh][dd][m] TRANSPOSED, tf32.
// ---------------------------------------------------------------------------
__global__ void reduce_build_kv(const float* __restrict__ part,
                                const float* __restrict__ bias,
                                const float* __restrict__ lv,
                                float* __restrict__ k, float* __restrict__ vt)
{
    const int idx = blockIdx.x * 256 + threadIdx.x;
    const int dd = idx & 63;
    const int m  = (idx >> 6) % 576;
    const int bh = idx / 36864;
    const int h  = bh & 7, b = bh >> 3;
    const int ck = h * 64 + dd;
    const long mrow = (long)(b * 576 + m) * 1024;
    float sk = bias[ck], sv = bias[512 + ck];
#pragma unroll
    for (int z = 0; z < 4; z++) {
        sk += part[z * 1179648 + mrow + ck];
        sv += part[z * 1179648 + mrow + 512 + ck];
    }
    k[idx] = __uint_as_float(f2tf(sk));
    float vv = sv + lv[(long)b * 294912 + h * 36864 + m * 64 + dd];
    vt[(long)bh * 36864 + dd * 576 + m] = __uint_as_float(f2tf(vv));
}

// w2[co][(i*4+j)*512 + ci] = tf32(w_sr[co][ci][i][j])
__global__ void reorder_w_kernel(const float* __restrict__ w,
                                 float* __restrict__ w2)
{
    const int tid = blockIdx.x * 256 + threadIdx.x;
    const int ci = tid & 511;
    const int s  = (tid >> 9) & 15;
    const int co = tid >> 13;
    w2[tid] = __uint_as_float(f2tf(w[(long)co * 8192 + ci * 16 + s]));
}

// ---------------------------------------------------------------------------
// FA2-style tf32 attention, cp.async + double-buffered K/V.
// bh0: head-batch offset (batch split for tail overlap with proj).
// ---------------------------------------------------------------------------
#define TPw 68
#define ATTN_SMEM (TPw * 384 * 4)

__global__ void __launch_bounds__(256, 2)
attn_flash(const float* __restrict__ qb,
           const float* __restrict__ kb,
           const float* __restrict__ vtb,
           float* __restrict__ ctx, int bh0)
{
    extern __shared__ float sm[];
    float*    Sw = sm;
    unsigned* KV = (unsigned*)(sm + 128 * TPw);

    const int t    = threadIdx.x;
    const int lane = t & 31, w = t >> 5;
    const int g  = lane >> 2, tg = lane & 3;
    const int bh = bh0 + blockIdx.y, b = bh >> 3, h = bh & 7;
    const int n0 = blockIdx.x * 128;

    const int tS = lane >> 3;
    const unsigned swB = (unsigned)__cvta_generic_to_shared(Sw);
    const unsigned kvB = (unsigned)__cvta_generic_to_shared(KV);
    const unsigned aOff = ((w * 16 + (tS & 1) * 8 + (lane & 7)) * TPw
                           + (tS >> 1) * 4) * 4;
    const unsigned bOff = (((tS >> 1) * 8 + (lane & 7)) * TPw
                           + (tS & 1) * 4) * 4;
    constexpr unsigned BUFB = 128 * TPw * 4;
    constexpr unsigned VOFF = 64 * TPw * 4;

    auto loadQ = [&]() {
#pragma unroll
        for (int i = 0; i < 8; i++) {
            int c = i * 256 + t;
            int row = c >> 4, off = (c & 15) * 4;
            cpa16(swB + (row * TPw + off) * 4,
                  qb + (long)(b * 9216 + n0 + row) * 512 + h * 64 + off);
        }
    };
    auto loadKV = [&](int ch, int buf) {
#pragma unroll
        for (int i = 0; i < 4; i++) {
            int c = i * 256 + t;
            int row = c >> 4, off = (c & 15) * 4;
            cpa16(kvB + buf * BUFB + (row * TPw + off) * 4,
                  kb + (long)(bh * 576 + ch * 64 + row) * 64 + off);
            cpa16(kvB + buf * BUFB + VOFF + (row * TPw + off) * 4,
                  vtb + (long)bh * 36864 + row * 576 + ch * 64 + off);
        }
    };

    loadQ();
    loadKV(0, 0);
    cpa_commit();
    cpa_wait0();
    __syncthreads();

    unsigned Qf[8][4];
#pragma unroll
    for (int kk = 0; kk < 8; kk++)
        ldsm4(Qf[kk], swB + aOff + kk * 32);

    float O[8][4];
#pragma unroll
    for (int nd = 0; nd < 8; nd++)
#pragma unroll
        for (int c = 0; c < 4; c++) O[nd][c] = 0.f;
    float m0 = -1e30f, l0 = 0.f, m1 = -1e30f, l1 = 0.f;

    int buf = 0;
    for (int ch = 0; ch < 9; ch++) {
        const bool more = (ch + 1 < 9);
        if (more) { loadKV(ch + 1, buf ^ 1); cpa_commit(); }

        const unsigned ksB = kvB + buf * BUFB + bOff;
        const unsigned vsB = kvB + buf * BUFB + VOFF + bOff;

        float acc[8][4];
#pragma unroll
        for (int ni = 0; ni < 8; ni++)
#pragma unroll
            for (int c = 0; c < 4; c++) acc[ni][c] = 0.f;
#pragma unroll
        for (int kk = 0; kk < 8; kk++) {
            unsigned bf[8][2];
#pragma unroll
            for (int p = 0; p < 4; p++) {
                unsigned q4[4];
                ldsm4(q4, ksB + p * (16 * TPw * 4) + kk * 32);
                bf[2 * p][0] = q4[0]; bf[2 * p][1] = q4[1];
                bf[2 * p + 1][0] = q4[2]; bf[2 * p + 1][1] = q4[3];
            }
#pragma unroll
            for (int ni = 0; ni < 8; ni++)
                mma8(acc[ni], Qf[kk], bf[ni]);
        }

        float cm0 = -1e30f, cm1 = -1e30f;
#pragma unroll
        for (int ni = 0; ni < 8; ni++) {
            cm0 = fmaxf(cm0, fmaxf(acc[ni][0], acc[ni][1]));
            cm1 = fmaxf(cm1, fmaxf(acc[ni][2], acc[ni][3]));
        }
        cm0 = fmaxf(cm0, __shfl_xor_sync(0xffffffffu, cm0, 1));
        cm0 = fmaxf(cm0, __shfl_xor_sync(0xffffffffu, cm0, 2));
        cm1 = fmaxf(cm1, __shfl_xor_sync(0xffffffffu, cm1, 1));
        cm1 = fmaxf(cm1, __shfl_xor_sync(0xffffffffu, cm1, 2));
        const float nm0 = fmaxf(m0, cm0), nm1 = fmaxf(m1, cm1);
        const float al0 = __expf(m0 - nm0), al1 = __expf(m1 - nm1);
        float sum0 = 0.f, sum1 = 0.f;
#pragma unroll
        for (int ni = 0; ni < 8; ni++) {
            float e0 = __expf(acc[ni][0] - nm0);
            float e1 = __expf(acc[ni][1] - nm0);
            float e2 = __expf(acc[ni][2] - nm1);
            float e3 = __expf(acc[ni][3] - nm1);
            acc[ni][0] = e0; acc[ni][1] = e1; acc[ni][2] = e2; acc[ni][3] = e3;
            sum0 += e0 + e1; sum1 += e2 + e3;
        }
        sum0 += __shfl_xor_sync(0xffffffffu, sum0, 1);
        sum0 += __shfl_xor_sync(0xffffffffu, sum0, 2);
        sum1 += __shfl_xor_sync(0xffffffffu, sum1, 1);
        sum1 += __shfl_xor_sync(0xffffffffu, sum1, 2);
        l0 = l0 * al0 + sum0; l1 = l1 * al1 + sum1;
        m0 = nm0; m1 = nm1;
#pragma unroll
        for (int nd = 0; nd < 8; nd++) {
            O[nd][0] *= al0; O[nd][1] *= al0;
            O[nd][2] *= al1; O[nd][3] *= al1;
        }

        float* SwW = Sw + w * 16 * TPw;
#pragma unroll
        for (int ni = 0; ni < 8; ni++) {
            *(float2*)&SwW[g * TPw + ni * 8 + 2 * tg] =
                make_float2(acc[ni][0], acc[ni][1]);
            *(float2*)&SwW[(g + 8) * TPw + ni * 8 + 2 * tg] =
                make_float2(acc[ni][2], acc[ni][3]);
        }
        __syncwarp();

#pragma unroll
        for (int kk = 0; kk < 8; kk++) {
            unsigned pa[4];
            ldsm4(pa, swB + aOff + kk * 32);
            unsigned bf[8][2];
#pragma unroll
            for (int p = 0; p < 4; p++) {
                unsigned q4[4];
                ldsm4(q4, vsB + p * (16 * TPw * 4) + kk * 32);
                bf[2 * p][0] = q4[0]; bf[2 * p][1] = q4[1];
                bf[2 * p + 1][0] = q4[2]; bf[2 * p + 1][1] = q4[3];
            }
#pragma unroll
            for (int nd = 0; nd < 8; nd++)
                mma8(O[nd], pa, bf[nd]);
        }

        if (more) {
            cpa_wait0();
            __syncthreads();
            buf ^= 1;
        }
    }

    const float inv0 = 1.f / l0, inv1 = 1.f / l1;
    const long row0 = (long)(b * 9216 + n0 + w * 16 + g) * 512 + h * 64;
    const long row1 = row0 + 8 * 512;
#pragma unroll
    for (int nd = 0; nd < 8; nd++) {
        const int c = nd * 8 + 2 * tg;
        *(float2*)(ctx + row0 + c) =
            make_float2(__uint_as_float(f2tf(O[nd][0] * inv0)),
                        __uint_as_float(f2tf(O[nd][1] * inv0)));
        *(float2*)(ctx + row1 + c) =
            make_float2(__uint_as_float(f2tf(O[nd][2] * inv1)),
                        __uint_as_float(f2tf(O[nd][3] * inv1)));
    }
}

// ---------------------------------------------------------------------------
// Launch pipeline: fork side chain; batch-split attn/proj tail overlap.
// ---------------------------------------------------------------------------
extern "C" void kernel_launch(void* const* d_in, const int* in_sizes, int n_in,
                              void* d_out, int out_size)
{
    (void)in_sizes; (void)n_in; (void)out_size;
    const float* x      = (const float*)d_in[0];
    const float* w_q    = (const float*)d_in[1];
    const float* b_q    = (const float*)d_in[2];
    const float* w_kv   = (const float*)d_in[3];
    const float* b_kv   = (const float*)d_in[4];
    const float* w_proj = (const float*)d_in[5];
    const float* b_proj = (const float*)d_in[6];
    const float* w_sr   = (const float*)d_in[7];
    const float* b_sr   = (const float*)d_in[8];
    const float* ln_g   = (const float*)d_in[9];
    const float* ln_b   = (const float*)d_in[10];
    const float* lAq    = (const float*)d_in[11];
    const float* lBq    = (const float*)d_in[12];
    const float* lAv    = (const float*)d_in[13];
    const float* lBv    = (const float*)d_in[14];

    float *q, *xs, *lv, *k, *v, *ctx, *w2, *part;
    float *bq8, *weffq, *weffv, *wkv2, *wp2;
    cudaGetSymbolAddress((void**)&q,     g_q);
    cudaGetSymbolAddress((void**)&xs,    g_xs);
    cudaGetSymbolAddress((void**)&lv,    g_lv);
    cudaGetSymbolAddress((void**)&k,     g_k);
    cudaGetSymbolAddress((void**)&v,     g_v);
    cudaGetSymbolAddress((void**)&ctx,   g_ctx);
    cudaGetSymbolAddress((void**)&w2,    g_w2);
    cudaGetSymbolAddress((void**)&part,  g_part);
    cudaGetSymbolAddress((void**)&bq8,   g_bq8);
    cudaGetSymbolAddress((void**)&weffq, g_weffq);
    cudaGetSymbolAddress((void**)&weffv, g_weffv);
    cudaGetSymbolAddress((void**)&wkv2,  g_wkv2);
    cudaGetSymbolAddress((void**)&wp2,   g_wp2);

    static cudaStream_t s2 = nullptr;
    static cudaEvent_t evF = nullptr, evJ = nullptr, evA = nullptr, evP = nullptr;
    if (!s2) {
        cudaStreamCreateWithFlags(&s2, cudaStreamNonBlocking);
        cudaEventCreateWithFlags(&evF, cudaEventDisableTiming);
        cudaEventCreateWithFlags(&evJ, cudaEventDisableTiming);
        cudaEventCreateWithFlags(&evA, cudaEventDisableTiming);
        cudaEventCreateWithFlags(&evP, cudaEventDisableTiming);
    }

    dim3 blk(256);
    const int smem128 = 2 * 256 * 36 * 4;   // 73728
    cudaFuncSetAttribute(gemm_tf32<128, 0>,
                         cudaFuncAttributeMaxDynamicSharedMemorySize, smem128);
    cudaFuncSetAttribute(gemm_tf32<128, 1>,
                         cudaFuncAttributeMaxDynamicSharedMemorySize, smem128);
    cudaFuncSetAttribute(attn_flash,
                         cudaFuncAttributeMaxDynamicSharedMemorySize, ATTN_SMEM);

    // ---- fork ----
    cudaEventRecord(evF, 0);
    cudaStreamWaitEvent(s2, evF, 0);

    // ---- side chain (stream s2): xs / k / v ----
    reorder_w_kernel<<<16384, blk, 0, s2>>>(w_sr, w2);
    cvt_tf32<<<512, blk, 0, s2>>>(w_kv, wkv2);
    make_weff<<<1024, blk, 0, s2>>>(nullptr, lBv, lAv, weffv);
    gemm_tf32<128, 1><<<dim3(4, 9, 8), blk, smem128, s2>>>(
        1152, 512, 8192, x, 512, w2, 8192, nullptr, 1.f, nullptr, 512,
        1024, part, 0);
    reduce_ln<<<1152, 128, 0, s2>>>(part, b_sr, ln_g, ln_b, xs);
    gemm_tf32<128, 0><<<dim3(8, 9, 4), blk, smem128, s2>>>(
        1152, 1024, 512, xs, 512, wkv2, 512, nullptr, 1.f, nullptr, 1024,
        128, part, 0);
    gemm_tf32<128, 0><<<dim3(4, 9, 1), blk, smem128, s2>>>(
        1152, 512, 512, xs, 512, weffv, 512, nullptr, 1.f, lv, 512,
        512, nullptr, 0);
    reduce_build_kv<<<2304, blk, 0, s2>>>(part, b_kv, lv, k, v);
    cudaEventRecord(evJ, s2);

    // ---- main chain: q = (X @ Weff_q^T) * 0.125 + bq8, tf32-rounded ----
    prep_bq<<<2, blk>>>(b_q, bq8);
    make_weff<<<1024, blk>>>(w_q, lBq, lAq, weffq);
    cvt_tf32<<<256, blk>>>(w_proj, wp2);
    gemm_tf32<128, 0><<<dim3(4, 144, 1), blk, smem128>>>(
        18432, 512, 512, x, 512, weffq, 512, bq8, 0.125f, q, 512,
        512, nullptr, 1);

    // ---- join, then batch-split tail: attn(b1) overlaps proj(b0) ----
    cudaStreamWaitEvent(0, evJ, 0);

    attn_flash<<<dim3(72, 8), blk, ATTN_SMEM>>>(q, k, v, ctx, 0);   // b=0
    cudaEventRecord(evA, 0);
    attn_flash<<<dim3(72, 8), blk, ATTN_SMEM>>>(q, k, v, ctx, 8);   // b=1

    // proj(b0) on s2, concurrent with attn(b1)
    cudaStreamWaitEvent(s2, evA, 0);
    gemm_tf32<128, 0><<<dim3(4, 72, 1), blk, smem128, s2>>>(
        9216, 512, 512, ctx, 512, wp2, 512, b_proj, 1.f, (float*)d_out,
        512, 512, nullptr, 0);
    cudaEventRecord(evP, s2);

    // proj(b1) on main
    gemm_tf32<128, 0><<<dim3(4, 72, 1), blk, smem128>>>(
        9216, 512, 512, ctx + (long)9216 * 512, 512, wp2, 512, b_proj, 1.f,
        (float*)d_out + (long)9216 * 512, 512, 512, nullptr, 0);
    cudaStreamWaitEvent(0, evP, 0);
}

// round 16
// speedup vs baseline: 1.0507x; 1.0002x over previous
#include <cuda_runtime.h>
#include <math.h>

// B=2, N=9216, C=512, HEAD=8, d=64, SR=4, H=W=96 -> Nkv=576, R=32
#define SCALING 0.125f

// ---------------------------------------------------------------------------
// Scratch
// ---------------------------------------------------------------------------
__device__ float g_q    [9437184];  // HEAD-MAJOR [bh][n][64], prescaled, tf32
__device__ float g_xs   [589824];   // (B*576,512) post-LN, tf32
__device__ float g_lv   [589824];
__device__ float g_k    [589824];   // (B*H,576,64) tf32
__device__ float g_v    [589824];   // (B*H,64,576) TRANSPOSED, tf32
__device__ float g_ctx  [9437184];  // tf32
__device__ float g_w2   [4194304];  // 512x8192 reordered conv weight, tf32
__device__ float g_part [4718592];  // split-K partials
__device__ float g_bq8  [512];      // b_q * 0.125
__device__ float g_weffq[262144];   // w_q + 0.125*lBq@lAq, tf32
__device__ float g_weffv[262144];   // 0.125*lBv@lAv, tf32
__device__ float g_wkv2 [524288];   // w_kv tf32
__device__ float g_wp2  [262144];   // w_proj tf32

// ---------------------------------------------------------------------------
// helpers
// ---------------------------------------------------------------------------
__device__ __forceinline__ unsigned f2tf(float x) {
    unsigned u;
    asm("cvt.rna.tf32.f32 %0, %1;" : "=r"(u) : "f"(x));
    return u;
}
__device__ __forceinline__ unsigned f2tf_u(unsigned x) {
    unsigned u;
    asm("cvt.rna.tf32.f32 %0, %1;" : "=r"(u) : "f"(__uint_as_float(x)));
    return u;
}
__device__ __forceinline__ void mma8(float* c, const unsigned* a, const unsigned* b) {
    asm volatile(
        "mma.sync.aligned.m16n8k8.row.col.f32.tf32.tf32.f32 "
        "{%0,%1,%2,%3}, {%4,%5,%6,%7}, {%8,%9}, {%0,%1,%2,%3};"
        : "+f"(c[0]), "+f"(c[1]), "+f"(c[2]), "+f"(c[3])
        : "r"(a[0]), "r"(a[1]), "r"(a[2]), "r"(a[3]),
          "r"(b[0]), "r"(b[1]));
}
__device__ __forceinline__ void ldsm4(unsigned* r, unsigned addr) {
    asm volatile(
        "ldmatrix.sync.aligned.m8n8.x4.shared.b16 {%0,%1,%2,%3}, [%4];"
        : "=r"(r[0]), "=r"(r[1]), "=r"(r[2]), "=r"(r[3]) : "r"(addr));
}
__device__ __forceinline__ void cpa16(unsigned dst, const void* src) {
    asm volatile("cp.async.cg.shared.global [%0], [%1], 16;" :: "r"(dst), "l"(src));
}
__device__ __forceinline__ void cpa_commit() {
    asm volatile("cp.async.commit_group;" ::: "memory");
}
__device__ __forceinline__ void cpa_wait0() {
    asm volatile("cp.async.wait_group 0;" ::: "memory");
}

// elementwise tf32 round
__global__ void cvt_tf32(const float* __restrict__ in, float* __restrict__ out)
{
    const int i = (blockIdx.x * 256 + threadIdx.x) * 4;
    float4 v = *(const float4*)(in + i);
    uint4 u;
    u.x = f2tf(v.x); u.y = f2tf(v.y); u.z = f2tf(v.z); u.w = f2tf(v.w);
    *(uint4*)(out + i) = u;
}

// Weff[o][i] = tf32( (base? base[o][i]:0) + SCALING * sum_r lB[o][r]*lA[r][i] )
__global__ void make_weff(const float* __restrict__ wbase,
                          const float* __restrict__ lB,   // 512x32
                          const float* __restrict__ lA,   // 32x512
                          float* __restrict__ out)        // 512x512
{
    const int i = blockIdx.x * 256 + threadIdx.x;
    const int col = i & 511, row = i >> 9;
    float s = 0.f;
#pragma unroll 8
    for (int r = 0; r < 32; r++)
        s += lB[row * 32 + r] * lA[r * 512 + col];
    s *= SCALING;
    if (wbase) s += wbase[i];
    out[i] = __uint_as_float(f2tf(s));
}

__global__ void prep_bq(const float* __restrict__ bq, float* __restrict__ bq8)
{
    const int i = blockIdx.x * 256 + threadIdx.x;
    if (i < 512) bq8[i] = bq[i] * 0.125f;
}

// ---------------------------------------------------------------------------
// tf32 GEMM, BK=32, 2-stage cp.async pipeline, ldmatrix frags.
// CVT=1: A raw fp32, A-fragments tf32-rounded in registers.
// CVT=0: A pre-rounded. B always pre-rounded tf32 in gmem.
//   C = scale*(A@B^T) (+bias)  [round_out]  [qhm: head-major C scatter]
// BM=128, BN=128; 256 threads; warps 4(M)x2(N).  kchunk%32==0.
// CONV=1: A gathered with SR-conv im2col mapping.
// ---------------------------------------------------------------------------
template <int BN, int CONV, int CVT>
__global__ void __launch_bounds__(256, 2)
gemm_tf32(int M, int N, int K,
          const float* __restrict__ A, int lda,
          const float* __restrict__ B, int ldb,
          const float* __restrict__ bias,
          float scale,
          float* __restrict__ C, int ldc,
          int kchunk, float* __restrict__ part,
          int round_out, int qhm)
{
    constexpr int NI = BN / 16;
    constexpr int P  = 36;
    extern __shared__ unsigned gsm[];
    unsigned* AsU = gsm;                   // 2 x 128 x P
    unsigned* BsU = gsm + 2 * 128 * P;     // 2 x BN x P

    const int t    = threadIdx.x;
    const int lane = t & 31, w = t >> 5;
    const int g  = lane >> 2, tg = lane & 3;
    const int wm = w >> 1,  wn = w & 1;
    const long m0 = (long)blockIdx.y * 128;
    const int  n0 = blockIdx.x * BN;
    const int  kb = blockIdx.z * kchunk;

    const int lrow = t >> 3;
    const int lko  = (t & 7) * 4;

    const int tS = lane >> 3;
    const unsigned asB = (unsigned)__cvta_generic_to_shared(AsU);
    const unsigned bsB = (unsigned)__cvta_generic_to_shared(BsU);
    const unsigned aOff = ((wm * 32 + (tS & 1) * 8 + (lane & 7)) * P
                           + (tS >> 1) * 4) * 4;
    const unsigned bOff = ((wn * (BN / 2) + (tS >> 1) * 8 + (lane & 7)) * P
                           + (tS & 1) * 4) * 4;

    float acc[2][NI][4];
#pragma unroll
    for (int mi = 0; mi < 2; mi++)
#pragma unroll
        for (int ni = 0; ni < NI; ni++)
#pragma unroll
            for (int c = 0; c < 4; c++) acc[mi][ni][c] = 0.f;

    long cr[4];
    if (CONV) {
#pragma unroll
        for (int i = 0; i < 4; i++) {
            int m = (int)m0 + i * 32 + lrow;
            int b = m / 576, p = m % 576, py = p / 24, px = p % 24;
            cr[i] = (long)b * 9216 + (py * 4) * 96 + px * 4;
        }
    }

    const int nIter = kchunk >> 5;

    auto issueTile = [&](int idx, int s) {
        const unsigned aS = asB + s * (128 * P * 4);
        const unsigned bS = bsB + s * (BN * P * 4);
        const int k0 = kb + (idx << 5);
        if (CONV) {
            const int tap = k0 >> 9;
            const int ci  = (k0 & 511) + lko;
            const long toff = (long)((tap >> 2) * 96 + (tap & 3)) * 512 + ci;
#pragma unroll
            for (int i = 0; i < 4; i++)
                cpa16(aS + ((i * 32 + lrow) * P + lko) * 4,
                      A + cr[i] * 512 + toff);
        } else {
#pragma unroll
            for (int i = 0; i < 4; i++)
                cpa16(aS + ((i * 32 + lrow) * P + lko) * 4,
                      A + (m0 + i * 32 + lrow) * lda + k0 + lko);
        }
#pragma unroll
        for (int i = 0; i < BN / 32; i++)
            cpa16(bS + ((i * 32 + lrow) * P + lko) * 4,
                  B + (long)(n0 + i * 32 + lrow) * ldb + k0 + lko);
        cpa_commit();
    };

    issueTile(0, 0);

    for (int it = 0; it < nIter; it++) {
        cpa_wait0();
        __syncthreads();
        if (it + 1 < nIter) issueTile(it + 1, (it + 1) & 1);

        const int s = it & 1;
        const unsigned aB = asB + s * (128 * P * 4) + aOff;
        const unsigned bB = bsB + s * (BN * P * 4) + bOff;
#pragma unroll
        for (int kk = 0; kk < 32; kk += 8) {
            unsigned af[2][4], bf[NI][2];
#pragma unroll
            for (int mi = 0; mi < 2; mi++) {
                ldsm4(af[mi], aB + mi * (16 * P * 4) + kk * 4);
                if (CVT) {
#pragma unroll
                    for (int j = 0; j < 4; j++) af[mi][j] = f2tf_u(af[mi][j]);
                }
            }
#pragma unroll
            for (int p = 0; p < NI / 2; p++) {
                unsigned q4[4];
                ldsm4(q4, bB + p * (16 * P * 4) + kk * 4);
                bf[2 * p][0] = q4[0]; bf[2 * p][1] = q4[1];
                bf[2 * p + 1][0] = q4[2]; bf[2 * p + 1][1] = q4[3];
            }
#pragma unroll
            for (int mi = 0; mi < 2; mi++)
#pragma unroll
                for (int ni = 0; ni < NI; ni++)
                    mma8(acc[mi][ni], af[mi], bf[ni]);
        }
    }

    if (gridDim.z == 1) {
#pragma unroll
        for (int mi = 0; mi < 2; mi++) {
            const long r0 = m0 + wm * 32 + mi * 16 + g;
            const long r1 = r0 + 8;
#pragma unroll
            for (int ni = 0; ni < NI; ni++) {
                const int c = n0 + wn * (BN / 2) + ni * 8 + 2 * tg;
                float v00 = scale * acc[mi][ni][0];
                float v01 = scale * acc[mi][ni][1];
                float v10 = scale * acc[mi][ni][2];
                float v11 = scale * acc[mi][ni][3];
                if (bias) {
                    float b0 = bias[c], b1 = bias[c + 1];
                    v00 += b0; v01 += b1; v10 += b0; v11 += b1;
                }
                if (round_out) {
                    v00 = __uint_as_float(f2tf(v00));
                    v01 = __uint_as_float(f2tf(v01));
                    v10 = __uint_as_float(f2tf(v10));
                    v11 = __uint_as_float(f2tf(v11));
                }
                if (qhm) {
                    // head-major scatter: [b*8+h][n][d]
                    const int h = c >> 6, d = c & 63;
                    const long b0r = r0 / 9216, n0r = r0 % 9216;
                    const long b1r = r1 / 9216, n1r = r1 % 9216;
                    *(float2*)(C + ((b0r * 8 + h) * 9216 + n0r) * 64 + d) =
                        make_float2(v00, v01);
                    *(float2*)(C + ((b1r * 8 + h) * 9216 + n1r) * 64 + d) =
                        make_float2(v10, v11);
                } else {
                    *(float2*)(C + r0 * ldc + c) = make_float2(v00, v01);
                    *(float2*)(C + r1 * ldc + c) = make_float2(v10, v11);
                }
            }
        }
    } else {
        float* Pp = part + (long)blockIdx.z * M * ldc;
#pragma unroll
        for (int mi = 0; mi < 2; mi++) {
            const long r0 = m0 + wm * 32 + mi * 16 + g;
            const long r1 = r0 + 8;
#pragma unroll
            for (int ni = 0; ni < NI; ni++) {
                const int c = n0 + wn * (BN / 2) + ni * 8 + 2 * tg;
                *(float2*)(Pp + r0 * ldc + c) =
                    make_float2(acc[mi][ni][0], acc[mi][ni][1]);
                *(float2*)(Pp + r1 * ldc + c) =
                    make_float2(acc[mi][ni][2], acc[mi][ni][3]);
            }
        }
    }
}

// ---------------------------------------------------------------------------
// Fused conv split-K reduce + bias + LayerNorm -> xs (tf32-rounded).
// ---------------------------------------------------------------------------
__global__ void reduce_ln(const float* __restrict__ part,
                          const float* __restrict__ bias,
                          const float* __restrict__ gam,
                          const float* __restrict__ bet,
                          float* __restrict__ out)
{
    const int row = blockIdx.x;
    const int t   = threadIdx.x;
    float v[4];
#pragma unroll
    for (int j = 0; j < 4; j++) {
        const int col = t + j * 128;
        float s = bias[col];
        const long off = (long)row * 512 + col;
#pragma unroll
        for (int z = 0; z < 8; z++) s += part[z * 589824 + off];
        v[j] = s;
    }
    float s  = v[0] + v[1] + v[2] + v[3];
    float s2 = v[0]*v[0] + v[1]*v[1] + v[2]*v[2] + v[3]*v[3];
#pragma unroll
    for (int o = 16; o > 0; o >>= 1) {
        s  += __shfl_xor_sync(0xffffffffu, s,  o);
        s2 += __shfl_xor_sync(0xffffffffu, s2, o);
    }
    __shared__ float ss[4], ss2[4];
    if ((t & 31) == 0) { ss[t >> 5] = s; ss2[t >> 5] = s2; }
    __syncthreads();
    s  = ss[0]  + ss[1]  + ss[2]  + ss[3];
    s2 = ss2[0] + ss2[1] + ss2[2] + ss2[3];
    const float mean = s * (1.f / 512.f);
    const float var  = s2 * (1.f / 512.f) - mean * mean;
    const float inv  = rsqrtf(var + 1e-5f);
    float* o = out + (long)row * 512;
#pragma unroll
    for (int j = 0; j < 4; j++) {
        const int col = t + j * 128;
        o[col] = __uint_as_float(f2tf((v[j] - mean) * inv * gam[col] + bet[col]));
    }
}

// ---------------------------------------------------------------------------
// Fused kv split-K reduce + bias + head split + LoRA-v fixup.
// ---------------------------------------------------------------------------
__global__ void reduce_build_kv(const float* __restrict__ part,
                                const float* __restrict__ bias,
                                const float* __restrict__ lv,
                                float* __restrict__ k, float* __restrict__ vt)
{
    const int idx = blockIdx.x * 256 + threadIdx.x;
    const int dd = idx & 63;
    const int m  = (idx >> 6) % 576;
    const int bh = idx / 36864;
    const int h  = bh & 7, b = bh >> 3;
    const int ck = h * 64 + dd;
    const long mrow = (long)(b * 576 + m) * 1024;
    float sk = bias[ck], sv = bias[512 + ck];
#pragma unroll
    for (int z = 0; z < 4; z++) {
        sk += part[z * 1179648 + mrow + ck];
        sv += part[z * 1179648 + mrow + 512 + ck];
    }
    k[idx] = __uint_as_float(f2tf(sk));
    float vv = sv + lv[(long)b * 294912 + h * 36864 + m * 64 + dd];
    vt[(long)bh * 36864 + dd * 576 + m] = __uint_as_float(f2tf(vv));
}

// w2[co][(i*4+j)*512 + ci] = tf32(w_sr[co][ci][i][j])
__global__ void reorder_w_kernel(const float* __restrict__ w,
                                 float* __restrict__ w2)
{
    const int tid = blockIdx.x * 256 + threadIdx.x;
    const int ci = tid & 511;
    const int s  = (tid >> 9) & 15;
    const int co = tid >> 13;
    w2[tid] = __uint_as_float(f2tf(w[(long)co * 8192 + ci * 16 + s]));
}

// ---------------------------------------------------------------------------
// FA2-style tf32 attention, cp.async + double-buffered K/V.
// q is HEAD-MAJOR [bh][n][64].  bh0: batch offset for tail overlap.
// ---------------------------------------------------------------------------
#define TPw 68
#define ATTN_SMEM (TPw * 384 * 4)

__global__ void __launch_bounds__(256, 2)
attn_flash(const float* __restrict__ qb,
           const float* __restrict__ kb,
           const float* __restrict__ vtb,
           float* __restrict__ ctx, int bh0)
{
    extern __shared__ float sm[];
    float*    Sw = sm;
    unsigned* KV = (unsigned*)(sm + 128 * TPw);

    const int t    = threadIdx.x;
    const int lane = t & 31, w = t >> 5;
    const int g  = lane >> 2, tg = lane & 3;
    const int bh = bh0 + blockIdx.y, b = bh >> 3, h = bh & 7;
    const int n0 = blockIdx.x * 128;

    const int tS = lane >> 3;
    const unsigned swB = (unsigned)__cvta_generic_to_shared(Sw);
    const unsigned kvB = (unsigned)__cvta_generic_to_shared(KV);
    const unsigned aOff = ((w * 16 + (tS & 1) * 8 + (lane & 7)) * TPw
                           + (tS >> 1) * 4) * 4;
    const unsigned bOff = (((tS >> 1) * 8 + (lane & 7)) * TPw
                           + (tS & 1) * 4) * 4;
    constexpr unsigned BUFB = 128 * TPw * 4;
    constexpr unsigned VOFF = 64 * TPw * 4;

    auto loadQ = [&]() {
#pragma unroll
        for (int i = 0; i < 8; i++) {
            int c = i * 256 + t;
            int row = c >> 4, off = (c & 15) * 4;
            cpa16(swB + (row * TPw + off) * 4,
                  qb + ((long)bh * 9216 + n0 + row) * 64 + off);
        }
    };
    auto loadKV = [&](int ch, int buf) {
#pragma unroll
        for (int i = 0; i < 4; i++) {
            int c = i * 256 + t;
            int row = c >> 4, off = (c & 15) * 4;
            cpa16(kvB + buf * BUFB + (row * TPw + off) * 4,
                  kb + (long)(bh * 576 + ch * 64 + row) * 64 + off);
            cpa16(kvB + buf * BUFB + VOFF + (row * TPw + off) * 4,
                  vtb + (long)bh * 36864 + row * 576 + ch * 64 + off);
        }
    };

    loadQ();
    loadKV(0, 0);
    cpa_commit();
    cpa_wait0();
    __syncthreads();

    unsigned Qf[8][4];
#pragma unroll
    for (int kk = 0; kk < 8; kk++)
        ldsm4(Qf[kk], swB + aOff + kk * 32);

    float O[8][4];
#pragma unroll
    for (int nd = 0; nd < 8; nd++)
#pragma unroll
        for (int c = 0; c < 4; c++) O[nd][c] = 0.f;
    float m0 = -1e30f, l0 = 0.f, m1 = -1e30f, l1 = 0.f;

    int buf = 0;
    for (int ch = 0; ch < 9; ch++) {
        const bool more = (ch + 1 < 9);
        if (more) { loadKV(ch + 1, buf ^ 1); cpa_commit(); }

        const unsigned ksB = kvB + buf * BUFB + bOff;
        const unsigned vsB = kvB + buf * BUFB + VOFF + bOff;

        float acc[8][4];
#pragma unroll
        for (int ni = 0; ni < 8; ni++)
#pragma unroll
            for (int c = 0; c < 4; c++) acc[ni][c] = 0.f;
#pragma unroll
        for (int kk = 0; kk < 8; kk++) {
            unsigned bf[8][2];
#pragma unroll
            for (int p = 0; p < 4; p++) {
                unsigned q4[4];
                ldsm4(q4, ksB + p * (16 * TPw * 4) + kk * 32);
                bf[2 * p][0] = q4[0]; bf[2 * p][1] = q4[1];
                bf[2 * p + 1][0] = q4[2]; bf[2 * p + 1][1] = q4[3];
            }
#pragma unroll
            for (int ni = 0; ni < 8; ni++)
                mma8(acc[ni], Qf[kk], bf[ni]);
        }

        float cm0 = -1e30f, cm1 = -1e30f;
#pragma unroll
        for (int ni = 0; ni < 8; ni++) {
            cm0 = fmaxf(cm0, fmaxf(acc[ni][0], acc[ni][1]));
            cm1 = fmaxf(cm1, fmaxf(acc[ni][2], acc[ni][3]));
        }
        cm0 = fmaxf(cm0, __shfl_xor_sync(0xffffffffu, cm0, 1));
        cm0 = fmaxf(cm0, __shfl_xor_sync(0xffffffffu, cm0, 2));
        cm1 = fmaxf(cm1, __shfl_xor_sync(0xffffffffu, cm1, 1));
        cm1 = fmaxf(cm1, __shfl_xor_sync(0xffffffffu, cm1, 2));
        const float nm0 = fmaxf(m0, cm0), nm1 = fmaxf(m1, cm1);
        const float al0 = __expf(m0 - nm0), al1 = __expf(m1 - nm1);
        float sum0 = 0.f, sum1 = 0.f;
#pragma unroll
        for (int ni = 0; ni < 8; ni++) {
            float e0 = __expf(acc[ni][0] - nm0);
            float e1 = __expf(acc[ni][1] - nm0);
            float e2 = __expf(acc[ni][2] - nm1);
            float e3 = __expf(acc[ni][3] - nm1);
            acc[ni][0] = e0; acc[ni][1] = e1; acc[ni][2] = e2; acc[ni][3] = e3;
            sum0 += e0 + e1; sum1 += e2 + e3;
        }
        sum0 += __shfl_xor_sync(0xffffffffu, sum0, 1);
        sum0 += __shfl_xor_sync(0xffffffffu, sum0, 2);
        sum1 += __shfl_xor_sync(0xffffffffu, sum1, 1);
        sum1 += __shfl_xor_sync(0xffffffffu, sum1, 2);
        l0 = l0 * al0 + sum0; l1 = l1 * al1 + sum1;
        m0 = nm0; m1 = nm1;
#pragma unroll
        for (int nd = 0; nd < 8; nd++) {
            O[nd][0] *= al0; O[nd][1] *= al0;
            O[nd][2] *= al1; O[nd][3] *= al1;
        }

        float* SwW = Sw + w * 16 * TPw;
#pragma unroll
        for (int ni = 0; ni < 8; ni++) {
            *(float2*)&SwW[g * TPw + ni * 8 + 2 * tg] =
                make_float2(acc[ni][0], acc[ni][1]);
            *(float2*)&SwW[(g + 8) * TPw + ni * 8 + 2 * tg] =
                make_float2(acc[ni][2], acc[ni][3]);
        }
        __syncwarp();

#pragma unroll
        for (int kk = 0; kk < 8; kk++) {
            unsigned pa[4];
            ldsm4(pa, swB + aOff + kk * 32);
            unsigned bf[8][2];
#pragma unroll
            for (int p = 0; p < 4; p++) {
                unsigned q4[4];
                ldsm4(q4, vsB + p * (16 * TPw * 4) + kk * 32);
                bf[2 * p][0] = q4[0]; bf[2 * p][1] = q4[1];
                bf[2 * p + 1][0] = q4[2]; bf[2 * p + 1][1] = q4[3];
            }
#pragma unroll
            for (int nd = 0; nd < 8; nd++)
                mma8(O[nd], pa, bf[nd]);
        }

        if (more) {
            cpa_wait0();
            __syncthreads();
            buf ^= 1;
        }
    }

    const float inv0 = 1.f / l0, inv1 = 1.f / l1;
    const long row0 = (long)(b * 9216 + n0 + w * 16 + g) * 512 + h * 64;
    const long row1 = row0 + 8 * 512;
#pragma unroll
    for (int nd = 0; nd < 8; nd++) {
        const int c = nd * 8 + 2 * tg;
        *(float2*)(ctx + row0 + c) =
            make_float2(__uint_as_float(f2tf(O[nd][0] * inv0)),
                        __uint_as_float(f2tf(O[nd][1] * inv0)));
        *(float2*)(ctx + row1 + c) =
            make_float2(__uint_as_float(f2tf(O[nd][2] * inv1)),
                        __uint_as_float(f2tf(O[nd][3] * inv1)));
    }
}

// ---------------------------------------------------------------------------
// Launch pipeline: 3 streams (main: q; s2: conv/kv side; s3: weight preps),
// batch-split attn/proj tail overlap.
// ---------------------------------------------------------------------------
extern "C" void kernel_launch(void* const* d_in, const int* in_sizes, int n_in,
                              void* d_out, int out_size)
{
    (void)in_sizes; (void)n_in; (void)out_size;
    const float* x      = (const float*)d_in[0];
    const float* w_q    = (const float*)d_in[1];
    const float* b_q    = (const float*)d_in[2];
    const float* w_kv   = (const float*)d_in[3];
    const float* b_kv   = (const float*)d_in[4];
    const float* w_proj = (const float*)d_in[5];
    const float* b_proj = (const float*)d_in[6];
    const float* w_sr   = (const float*)d_in[7];
    const float* b_sr   = (const float*)d_in[8];
    const float* ln_g   = (const float*)d_in[9];
    const float* ln_b   = (const float*)d_in[10];
    const float* lAq    = (const float*)d_in[11];
    const float* lBq    = (const float*)d_in[12];
    const float* lAv    = (const float*)d_in[13];
    const float* lBv    = (const float*)d_in[14];

    float *q, *xs, *lv, *k, *v, *ctx, *w2, *part;
    float *bq8, *weffq, *weffv, *wkv2, *wp2;
    cudaGetSymbolAddress((void**)&q,     g_q);
    cudaGetSymbolAddress((void**)&xs,    g_xs);
    cudaGetSymbolAddress((void**)&lv,    g_lv);
    cudaGetSymbolAddress((void**)&k,     g_k);
    cudaGetSymbolAddress((void**)&v,     g_v);
    cudaGetSymbolAddress((void**)&ctx,   g_ctx);
    cudaGetSymbolAddress((void**)&w2,    g_w2);
    cudaGetSymbolAddress((void**)&part,  g_part);
    cudaGetSymbolAddress((void**)&bq8,   g_bq8);
    cudaGetSymbolAddress((void**)&weffq, g_weffq);
    cudaGetSymbolAddress((void**)&weffv, g_weffv);
    cudaGetSymbolAddress((void**)&wkv2,  g_wkv2);
    cudaGetSymbolAddress((void**)&wp2,   g_wp2);

    static cudaStream_t s2 = nullptr, s3 = nullptr;
    static cudaEvent_t evF = nullptr, evJ = nullptr, evA = nullptr;
    static cudaEvent_t evP = nullptr, evW = nullptr;
    if (!s2) {
        cudaStreamCreateWithFlags(&s2, cudaStreamNonBlocking);
        cudaStreamCreateWithFlags(&s3, cudaStreamNonBlocking);
        cudaEventCreateWithFlags(&evF, cudaEventDisableTiming);
        cudaEventCreateWithFlags(&evJ, cudaEventDisableTiming);
        cudaEventCreateWithFlags(&evA, cudaEventDisableTiming);
        cudaEventCreateWithFlags(&evP, cudaEventDisableTiming);
        cudaEventCreateWithFlags(&evW, cudaEventDisableTiming);
    }

    dim3 blk(256);
    const int smem128 = 2 * 256 * 36 * 4;   // 73728
    cudaFuncSetAttribute(gemm_tf32<128, 0, 0>,
                         cudaFuncAttributeMaxDynamicSharedMemorySize, smem128);
    cudaFuncSetAttribute(gemm_tf32<128, 0, 1>,
                         cudaFuncAttributeMaxDynamicSharedMemorySize, smem128);
    cudaFuncSetAttribute(gemm_tf32<128, 1, 1>,
                         cudaFuncAttributeMaxDynamicSharedMemorySize, smem128);
    cudaFuncSetAttribute(attn_flash,
                         cudaFuncAttributeMaxDynamicSharedMemorySize, ATTN_SMEM);

    // ---- fork ----
    cudaEventRecord(evF, 0);
    cudaStreamWaitEvent(s2, evF, 0);
    cudaStreamWaitEvent(s3, evF, 0);

    // ---- s3: weight preps off the critical streams ----
    cvt_tf32<<<512, blk, 0, s3>>>(w_kv, wkv2);
    make_weff<<<1024, blk, 0, s3>>>(nullptr, lBv, lAv, weffv);
    cvt_tf32<<<256, blk, 0, s3>>>(w_proj, wp2);
    cudaEventRecord(evW, s3);

    // ---- side chain (stream s2): conv -> LN -> kv -> lv -> build k/v ----
    reorder_w_kernel<<<16384, blk, 0, s2>>>(w_sr, w2);
    gemm_tf32<128, 1, 1><<<dim3(4, 9, 8), blk, smem128, s2>>>(
        1152, 512, 8192, x, 512, w2, 8192, nullptr, 1.f, nullptr, 512,
        1024, part, 0, 0);
    reduce_ln<<<1152, 128, 0, s2>>>(part, b_sr, ln_g, ln_b, xs);
    cudaStreamWaitEvent(s2, evW, 0);
    gemm_tf32<128, 0, 0><<<dim3(8, 9, 4), blk, smem128, s2>>>(
        1152, 1024, 512, xs, 512, wkv2, 512, nullptr, 1.f, nullptr, 1024,
        128, part, 0, 0);
    gemm_tf32<128, 0, 0><<<dim3(4, 9, 1), blk, smem128, s2>>>(
        1152, 512, 512, xs, 512, weffv, 512, nullptr, 1.f, lv, 512,
        512, nullptr, 0, 0);
    reduce_build_kv<<<2304, blk, 0, s2>>>(part, b_kv, lv, k, v);
    cudaEventRecord(evJ, s2);

    // ---- main chain: q (head-major, prescaled, tf32-rounded) ----
    prep_bq<<<2, blk>>>(b_q, bq8);
    make_weff<<<1024, blk>>>(w_q, lBq, lAq, weffq);
    gemm_tf32<128, 0, 1><<<dim3(4, 144, 1), blk, smem128>>>(
        18432, 512, 512, x, 512, weffq, 512, bq8, 0.125f, q, 512,
        512, nullptr, 1, 1);

    // ---- join, then batch-split tail: attn(b1) overlaps proj(b0) ----
    cudaStreamWaitEvent(0, evJ, 0);

    attn_flash<<<dim3(72, 8), blk, ATTN_SMEM>>>(q, k, v, ctx, 0);   // b=0
    cudaEventRecord(evA, 0);
    attn_flash<<<dim3(72, 8), blk, ATTN_SMEM>>>(q, k, v, ctx, 8);   // b=1

    // proj(b0) on s2, concurrent with attn(b1)   (s2 already waited evW)
    cudaStreamWaitEvent(s2, evA, 0);
    gemm_tf32<128, 0, 0><<<dim3(4, 72, 1), blk, smem128, s2>>>(
        9216, 512, 512, ctx, 512, wp2, 512, b_proj, 1.f, (float*)d_out,
        512, 512, nullptr, 0, 0);
    cudaEventRecord(evP, s2);

    // proj(b1) on main
    cudaStreamWaitEvent(0, evW, 0);
    gemm_tf32<128, 0, 0><<<dim3(4, 72, 1), blk, smem128>>>(
        9216, 512, 512, ctx + (long)9216 * 512, 512, wp2, 512, b_proj, 1.f,
        (float*)d_out + (long)9216 * 512, 512, 512, nullptr, 0, 0);
    cudaStreamWaitEvent(0, evP, 0);
}